// round 17
// baseline (speedup 1.0000x reference)
#include <cuda_runtime.h>
#include <cuda.h>
#include <cstdint>
#include <math.h>

// ---------------------------------------------------------------------------
// A : TMA 2D tensor load (2 UTMALDG/block, box [144 floats x 32 images]) +
//     pipelined pooling halves + circuit closed form + per-block partials.
//     IPB=64, 256 threads, 1024 blocks.
// S : 1-block stats finalize -> g_sb.   C : pure normalize (1 float4/thread).
// ---------------------------------------------------------------------------

#define B_TOTAL 65536
#define IPB     64
#define NB      (B_TOTAL / IPB)         // 1024 blocks
#define THREADS 256
#define HALF_BYTES (32 * 576)           // 18432 per half-tile

__device__ __align__(16) float g_part[NB * 8];  // per-block [sum0..3, sumsq0..3]
__device__ __align__(16) float g_sb[8];         // scale[4], bias[4]

__device__ __forceinline__ void mbar_wait(unsigned int mb) {
    asm volatile(
        "{\n\t.reg .pred p;\n\t"
        "WAIT_%=:\n\t"
        "mbarrier.try_wait.parity.shared.b64 p, [%0], 0, 0x989680;\n\t"
        "@!p bra WAIT_%=;\n\t}"
        :: "r"(mb) : "memory");
}

__global__ __launch_bounds__(THREADS)
void qfc_kernelA(const __grid_constant__ CUtensorMap tmap,
                 const float* __restrict__ pr,
                 float* __restrict__ out)
{
    __shared__ __align__(128) float sd[IPB][144];   // 36,864 B (dense TMA rows)
    __shared__ __align__(8) unsigned long long mbar[2];
    __shared__ float swarp[8][8];

    const int tid  = threadIdx.x;
    const int wid  = tid >> 5;
    const int lane = tid & 31;
    const int g    = tid & 3;           // qubit index
    const int img  = tid >> 2;          // image within block (0..63)
    const long ib  = (long)blockIdx.x * IPB;

    unsigned int mb0 = (unsigned int)__cvta_generic_to_shared(&mbar[0]);
    unsigned int mb1 = (unsigned int)__cvta_generic_to_shared(&mbar[1]);

    if (tid == 0) {
        asm volatile("mbarrier.init.shared.b64 [%0], 1;" :: "r"(mb0) : "memory");
        asm volatile("mbarrier.init.shared.b64 [%0], 1;" :: "r"(mb1) : "memory");
        asm volatile("fence.proxy.async.shared::cta;" ::: "memory");
    }
    __syncthreads();

    if (tid == 0) {
        const unsigned long long tm = (unsigned long long)&tmap;
        unsigned int d0 = (unsigned int)__cvta_generic_to_shared(&sd[0][0]);
        unsigned int d1 = (unsigned int)__cvta_generic_to_shared(&sd[32][0]);
        int y0 = (int)(ib);
        asm volatile("mbarrier.arrive.expect_tx.shared.b64 _, [%0], %1;"
                     :: "r"(mb0), "r"(HALF_BYTES) : "memory");
        asm volatile(
            "cp.async.bulk.tensor.2d.shared::cta.global.tile.mbarrier::complete_tx::bytes "
            "[%0], [%1, {%2, %3}], [%4];"
            :: "r"(d0), "l"(tm), "r"(0), "r"(y0), "r"(mb0) : "memory");
        asm volatile("mbarrier.arrive.expect_tx.shared.b64 _, [%0], %1;"
                     :: "r"(mb1), "r"(HALF_BYTES) : "memory");
        asm volatile(
            "cp.async.bulk.tensor.2d.shared::cta.global.tile.mbarrier::complete_tx::bytes "
            "[%0], [%1, {%2, %3}], [%4];"
            :: "r"(d1), "l"(tm), "r"(0), "r"(y0 + 32), "r"(mb1) : "memory");
    }

    const float phi  = pr[g * 2 + 0];
    const float lam  = pr[g * 2 + 1];
    const float clam = __cosf(lam);
    const float k2   = __sinf(lam) * __sinf(phi);

    float myz = 0.f;
    const int krot = (lane >> 3) & 3;   // row-phase rotation: caps smem conflicts

    auto pool_z = [&]() {
        const float* base = &sd[img][g * 6];
        float a = 0.f;
#pragma unroll
        for (int rr = 0; rr < 6; rr++) {
            int r = rr + krot;
            r -= (r >= 6) ? 6 : 0;
            const float* row = base + r * 24;
            a += ((row[0] + row[1]) + (row[2] + row[3])) + (row[4] + row[5]);
        }
        const float theta = a * (1.f / 36.f);
        float st, ct;
        __sincosf(theta, &st, &ct);
        myz = clam * ct + k2 * st;
    };

    // half 0: images 0..31 (threads 0..127)
    mbar_wait(mb0);
    __syncthreads();
    if (tid < 128) pool_z();

    // half 1: images 32..63 (threads 128..255)
    mbar_wait(mb1);
    __syncthreads();
    if (tid >= 128) pool_z();

    // gather the 4 z's of this image (adjacent lanes)
    const unsigned lbase = lane & ~3u;
    const float z0 = __shfl_sync(0xffffffffu, myz, lbase + 0);
    const float z1 = __shfl_sync(0xffffffffu, myz, lbase + 1);
    const float z2 = __shfl_sync(0xffffffffu, myz, lbase + 2);
    const float z3 = __shfl_sync(0xffffffffu, myz, lbase + 3);

    float acc[8] = {0.f, 0.f, 0.f, 0.f, 0.f, 0.f, 0.f, 0.f};
    if (g == 0) {
        const float o0 = z0;
        const float o1 = o0 * z1;
        const float o2 = o1 * z2;
        const float o3 = o2 * z3;
        ((float4*)out)[ib + img] = make_float4(o0, o1, o2, o3);
        acc[0] = o0;      acc[1] = o1;      acc[2] = o2;      acc[3] = o3;
        acc[4] = o0 * o0; acc[5] = o1 * o1; acc[6] = o2 * o2; acc[7] = o3 * o3;
    }

    // warp reduction over lanes 0,4,..,28 then cross-warp combine
#pragma unroll
    for (int k = 0; k < 8; k++) {
#pragma unroll
        for (int off = 16; off >= 4; off >>= 1)
            acc[k] += __shfl_down_sync(0xffffffffu, acc[k], off);
    }
    if (lane == 0) {
#pragma unroll
        for (int k = 0; k < 8; k++) swarp[wid][k] = acc[k];
    }
    __syncthreads();
    if (tid < 8) {
        float r = 0.f;
#pragma unroll
        for (int w = 0; w < 8; w++) r += swarp[w][tid];
        g_part[blockIdx.x * 8 + tid] = r;
    }
}

// ---- S: single-block stats finalize -> g_sb --------------------------------
__global__ __launch_bounds__(256)
void qfc_kernelS(const float* __restrict__ gamma,
                 const float* __restrict__ beta)
{
    __shared__ float swarp[8][8];
    const int tid  = threadIdx.x;
    const int wrp  = tid >> 5;
    const int lane = tid & 31;

    const float4* __restrict__ p4 = (const float4*)g_part;   // 2048 float4
    float r[8] = {0.f, 0.f, 0.f, 0.f, 0.f, 0.f, 0.f, 0.f};
#pragma unroll
    for (int it = 0; it < NB / 256; it++) {                   // 4 iters
        int j = tid + it * 256;
        float4 s  = __ldcg(&p4[j * 2]);
        float4 qq = __ldcg(&p4[j * 2 + 1]);
        r[0] += s.x;  r[1] += s.y;  r[2] += s.z;  r[3] += s.w;
        r[4] += qq.x; r[5] += qq.y; r[6] += qq.z; r[7] += qq.w;
    }
#pragma unroll
    for (int k = 0; k < 8; k++) {
#pragma unroll
        for (int off = 16; off; off >>= 1)
            r[k] += __shfl_down_sync(0xffffffffu, r[k], off);
    }
    if (lane == 0) {
#pragma unroll
        for (int k = 0; k < 8; k++) swarp[wrp][k] = r[k];
    }
    __syncthreads();

    if (tid < 4) {
        float ss = 0.f, qq = 0.f;
#pragma unroll
        for (int w = 0; w < 8; w++) { ss += swarp[w][tid]; qq += swarp[w][4 + tid]; }
        const float mean = ss * (1.f / (float)B_TOTAL);
        const float ex2  = qq * (1.f / (float)B_TOTAL);
        const float var  = fmaxf(ex2 - mean * mean, 0.f);
        const float inv  = rsqrtf(var + 1e-5f);
        const float sc   = gamma[tid] * inv;
        g_sb[tid]     = sc;
        g_sb[4 + tid] = beta[tid] - mean * sc;
    }
}

// ---- C: pure normalize, 1 float4 per thread --------------------------------
__global__ __launch_bounds__(256)
void qfc_kernelC(float* __restrict__ out)
{
    const float4 scv = *(const float4*)&g_sb[0];
    const float4 biv = *(const float4*)&g_sb[4];
    const int i = blockIdx.x * 256 + threadIdx.x;    // 65536 threads total
    float4 v = ((float4*)out)[i];
    v.x = v.x * scv.x + biv.x;
    v.y = v.y * scv.y + biv.y;
    v.z = v.z * scv.z + biv.z;
    v.w = v.w * scv.w + biv.w;
    ((float4*)out)[i] = v;
}

typedef CUresult (*PFN_encodeTiled)(
    CUtensorMap*, CUtensorMapDataType, cuuint32_t, void*,
    const cuuint64_t*, const cuuint64_t*, const cuuint32_t*, const cuuint32_t*,
    CUtensorMapInterleave, CUtensorMapSwizzle, CUtensorMapL2promotion,
    CUtensorMapFloatOOBfill);

extern "C" void kernel_launch(void* const* d_in, const int* in_sizes, int n_in,
                              void* d_out, int out_size)
{
    const float* x      = (const float*)d_in[0];   // [65536,1,24,24]
    const float* params = (const float*)d_in[1];   // [4,2]
    const float* gamma  = (const float*)d_in[2];   // [4]
    const float* beta   = (const float*)d_in[3];   // [4]
    float* out = (float*)d_out;                    // [65536,4]

    // host-side tensormap encode via driver entry point (no -lcuda needed)
    void* fn = nullptr;
    cudaDriverEntryPointQueryResult qres;
    cudaGetDriverEntryPointByVersion("cuTensorMapEncodeTiled", &fn, 12000,
                                     cudaEnableDefault, &qres);
    PFN_encodeTiled encode = (PFN_encodeTiled)fn;

    CUtensorMap tmap;
    cuuint64_t gdim[2]    = {144, (cuuint64_t)B_TOTAL};  // 144 floats x 65536 rows
    cuuint64_t gstride[1] = {2304};                      // bytes between rows
    cuuint32_t box[2]     = {144, 32};
    cuuint32_t estr[2]    = {1, 1};
    encode(&tmap, CU_TENSOR_MAP_DATA_TYPE_FLOAT32, 2, (void*)x,
           gdim, gstride, box, estr,
           CU_TENSOR_MAP_INTERLEAVE_NONE, CU_TENSOR_MAP_SWIZZLE_NONE,
           CU_TENSOR_MAP_L2_PROMOTION_L2_128B, CU_TENSOR_MAP_FLOAT_OOB_FILL_NONE);

    qfc_kernelA<<<NB, THREADS>>>(tmap, params, out);
    qfc_kernelS<<<1, 256>>>(gamma, beta);
    qfc_kernelC<<<B_TOTAL / 256, 256>>>(out);
}